// round 17
// baseline (speedup 1.0000x reference)
#include <cuda_runtime.h>

// Problem constants (fixed by setup_inputs: H=480, W=1024, S=32, margin=10, step=4)
#define HH     480
#define WW     1024
#define SS     32
#define HWIMG  (HH*WW)          // 491520
#define NSLOT  61440            // 2*H*W/step^2
#define GXC    252
#define GYC    116
#define GG     (GXC*GYC)        // 29232
#define MARG   10
#define BB     240              // persistent linker grid: 240 blocks x 256 = NSLOT threads
#define TT     256
#define NWARP  (TT/32)          // 8
#define WPI    (HWIMG/32)       // 15360 bitmask words per step
#define WPR    8                // occupancy words per grid row (256 bits >= GXC)
#define PWORDS 1024             // padded occupancy words (>= GYC*WPR = 928)
#define NSUB   8
#define SUBQ   (BB/NSUB)        // 30
#define TPS    960              // tiles per on-mask slice (512 px per tile)
#define NTK    (30*TPS)         // tickets per run: slices 1..30

// Scratch (device globals; no allocations allowed)
__device__ __align__(16) unsigned g_bits[3][PWORDS];  // occupancy, 3-buffer rotation (R13 race-free)
__device__ __align__(128) unsigned g_on[(SS-1)*WPI];  // on-mask; slice 0 by prologue, 1..30 stolen
__device__ int g_slotCnt[2][NWARP][BB];               // parity-buffered (warp-row, block) free counts
__device__ unsigned g_onCnt[SS-1];                    // MONOTONIC per-slice tile counters (idx 1..30)
__device__ unsigned g_ticket;                         // MONOTONIC work ticket
__device__ unsigned g_epoch;                          // MONOTONIC run counter
__device__ unsigned g_tgt;                            // this run's per-slice counter target
__device__ unsigned g_tkb;                            // this run's ticket base (snapshot)
// Monotonic counting barrier: counters NEVER reset (replay-safe); release = single gen bump.
struct __align__(128) PadCnt { unsigned v; unsigned pad[31]; };
__device__ PadCnt g_barSub[NSUB];
__device__ PadCnt g_barMaster;
__device__ __align__(128) volatile unsigned g_barGen;

// empty pattern: pad bits (ix>=252 in-row, rows>=GYC) are permanently "occupied"
__device__ __forceinline__ unsigned epat(int w) {
    return (w >= GYC*WPR) ? 0xFFFFFFFFu : (((w & 7) == 7) ? 0xF0000000u : 0u);
}

__device__ __forceinline__ void l2_prefetch(const void* p) {
    asm volatile("prefetch.global.L2 [%0];" :: "l"(p));
}

// ---- math helpers: byte-identical to R1..R16 (rel_err was 0.0) ----
__device__ __forceinline__ float bil4(float s00, float s01, float s10, float s11,
                                      float w00, float w01, float w10, float w11) {
    return fmaf(s11, w11, fmaf(s10, w10, fmaf(s00, w00, __fmul_rn(s01, w01))));
}

struct BilW {
    int ix0, ix1, iy0, iy1;
    float w00, w01, w10, w11;
};

__device__ __forceinline__ BilW mkw(float x, float y) {
    BilW b;
    float x0f = floorf(x), y0f = floorf(y);
    float wx1 = __fsub_rn(x, x0f); float wx0 = __fsub_rn(1.0f, wx1);
    float wy1 = __fsub_rn(y, y0f); float wy0 = __fsub_rn(1.0f, wy1);
    int ix0 = (int)x0f; ix0 = ix0 < 0 ? 0 : (ix0 > WW-1 ? WW-1 : ix0);
    int iy0 = (int)y0f; iy0 = iy0 < 0 ? 0 : (iy0 > HH-1 ? HH-1 : iy0);
    b.ix0 = ix0; b.ix1 = (ix0+1 > WW-1) ? WW-1 : ix0+1;
    b.iy0 = iy0; b.iy1 = (iy0+1 > HH-1) ? HH-1 : iy0+1;
    b.w00 = __fmul_rn(wy0, wx0); b.w01 = __fmul_rn(wy0, wx1);
    b.w10 = __fmul_rn(wy1, wx0); b.w11 = __fmul_rn(wy1, wx1);
    return b;
}

__device__ __forceinline__ float on_at(const float* __restrict__ fb0,
                                       const float* __restrict__ fb1,
                                       float a0, float a1, int py, int px) {
    float xt = __fadd_rn((float)px, a0);
    float yt = __fadd_rn((float)py, a1);
    BilW b = mkw(xt, yt);
    float f00 = fb0[b.iy0*WW+b.ix0], f01 = fb0[b.iy0*WW+b.ix1];
    float f10 = fb0[b.iy1*WW+b.ix0], f11 = fb0[b.iy1*WW+b.ix1];
    float g00 = fb1[b.iy0*WW+b.ix0], g01 = fb1[b.iy0*WW+b.ix1];
    float g10 = fb1[b.iy1*WW+b.ix0], g11 = fb1[b.iy1*WW+b.ix1];
    float f0 = bil4(f00, f01, f10, f11, b.w00, b.w01, b.w10, b.w11);
    float f1 = bil4(g00, g01, g10, g11, b.w00, b.w01, b.w10, b.w11);
    float d0 = __fadd_rn(a0, f0), d1 = __fadd_rn(a1, f1);
    float diff = __fsqrt_rn(fmaf(d1, d1, __fmul_rn(d0, d0)));
    float m1 = __fsqrt_rn(fmaf(a1, a1, __fmul_rn(a0, a0)));
    float m2 = __fsqrt_rn(fmaf(f1, f1, __fmul_rn(f0, f0)));
    float mag = __fmul_rn(0.5f, __fadd_rn(m1, m2));
    return (diff <= fmaf(0.01f, mag, 0.1f)) ? 1.0f : 0.0f;
}

// ---- steal one mask tile (512 px of slices 1..30). Producer recipe = R11/R12 (proven):
// __stcg data -> threadfence -> syncthreads -> strong atomicAdd signal.
__device__ __forceinline__ bool steal_one(const float* __restrict__ ff,
                                          const float* __restrict__ fb,
                                          int tid, unsigned tkb, int* shtk) {
    if (tid == 0) *shtk = (int)(atomicAdd(&g_ticket, 1u) - tkb);
    __syncthreads();
    int tk = *shtk;
    __syncthreads();
    if (tk >= NTK) return false;                    // uniform across block
    int slice = 1 + tk / TPS;
    int base  = (tk - (slice - 1) * TPS) * 512;
    const float* ff0 = ff + (size_t)slice * 2 * HWIMG;
    const float* ff1 = ff0 + HWIMG;
    const float* fb0 = fb + (size_t)slice * 2 * HWIMG;
    const float* fb1 = fb0 + HWIMG;
    #pragma unroll
    for (int k = 0; k < 2; k++) {
        int p = base + k*TT + tid;
        float a0 = ff0[p], a1 = ff1[p];
        float on = on_at(fb0, fb1, a0, a1, p >> 10, p & 1023);
        unsigned m = __ballot_sync(0xffffffffu, on != 0.0f);
        if ((tid & 31) == 0) __stcg(&g_on[slice*WPI + (p >> 5)], m);
    }
    __threadfence();
    __syncthreads();
    if (tid == 0) atomicAdd(&g_onCnt[slice], 1u);
    return true;
}

// plain monotonic grid barrier (init only — ticket base not yet published)
__device__ __forceinline__ void gridbar_plain(int b, int tid) {
    __syncthreads();
    if (tid == 0) {
        __threadfence();
        unsigned gen = g_barGen;
        bool last = false;
        if (atomicAdd(&g_barSub[b & (NSUB-1)].v, 1u) == (gen+1u)*SUBQ - 1u)
            if (atomicAdd(&g_barMaster.v, 1u) == (gen+1u)*NSUB - 1u) last = true;
        if (last) { __threadfence(); g_barGen = gen + 1u; }
        else { while (g_barGen == gen) { } }
    }
    __syncthreads();
}

// grid barrier that steals mask tiles while waiting (arrive FIRST, then steal+poll)
__device__ __forceinline__ void gridbar_steal(const float* __restrict__ ff,
                                              const float* __restrict__ fb,
                                              int b, int tid, unsigned tkb,
                                              int* shtk, unsigned* shw) {
    __syncthreads();
    if (tid == 0) {
        __threadfence();
        unsigned gen = g_barGen;
        shw[0] = gen;
        bool last = false;
        if (atomicAdd(&g_barSub[b & (NSUB-1)].v, 1u) == (gen+1u)*SUBQ - 1u)
            if (atomicAdd(&g_barMaster.v, 1u) == (gen+1u)*NSUB - 1u) last = true;
        if (last) { __threadfence(); g_barGen = gen + 1u; }
    }
    __syncthreads();
    unsigned gen = shw[0];
    while (true) {
        if (tid == 0) shw[1] = (g_barGen != gen) ? 1u : 0u;
        __syncthreads();
        if (shw[1]) break;                          // uniform
        __syncthreads();
        if (!steal_one(ff, fb, tid, tkb, shtk)) {
            if (tid == 0) __nanosleep(256);
            __syncthreads();
        }
    }
    __syncthreads();
}

// wait for slice s (strong RMW poll), stealing tiles while short
__device__ __forceinline__ void wait_slice(const float* __restrict__ ff,
                                           const float* __restrict__ fb,
                                           int tid, int s, unsigned tgt, unsigned tkb,
                                           int* shtk, unsigned* shw) {
    while (true) {
        if (tid == 0) shw[1] = (atomicAdd(&g_onCnt[s], 0u) >= tgt) ? 1u : 0u;
        __syncthreads();
        if (shw[1]) break;                          // uniform
        __syncthreads();
        if (!steal_one(ff, fb, tid, tkb, shtk)) {
            if (tid == 0) __nanosleep(256);
            __syncthreads();
        }
    }
    __syncthreads();
}

// ---------------- ONE kernel: R15 linker + work-stealing on-mask production ----------------
__global__ void __launch_bounds__(TT, 2) k_linker(const float* __restrict__ ff,
                                                  const float* __restrict__ fb,
                                                  float* __restrict__ out) {
    const int tid  = threadIdx.x;
    const int b    = blockIdx.x;
    const int lane = tid & 31;
    const int wid  = tid >> 5;
    const int t    = (b + BB*wid)*32 + lane;   // swizzled slot id
    const int u    = b * TT + tid;             // linear id (prologue / prefetch striping)

    float* X  = out;
    float* Y  = out + SS*NSLOT;
    float* St = out + 2*SS*NSLOT;

    __shared__ unsigned sh_bits[PWORDS];       // 4KB: full occupancy snapshot
    __shared__ int sh_pre[TT];                 // exclusive zero-count prefix per 4-word chunk
    __shared__ int sh_rowtot[NWARP], sh_wsum[NWARP], sh_woff[NWARP];
    __shared__ int sh_nf, sh_nc;
    __shared__ int sh_tk;
    __shared__ unsigned sh_w[2];

    // ---- init: per-thread state, occupancy buffers, slice-0 prologue, run bookkeeping ----
    float myX, myY, mySt;
    {
        bool ing = t < GG;
        myX  = ing ? (float)(MARG + 4*(t % GXC)) : 0.0f;
        myY  = ing ? (float)(MARG + 4*(t / GXC)) : 0.0f;
        mySt = ing ? 0.0f : -1.0f;
        X[t] = myX; Y[t] = myY;            // row 0
    }
    if (b < 12) {                           // 12 blocks x 256 = 3072 = 3*PWORDS
        int w = ((b & 3) << 8) + tid;
        g_bits[b >> 2][w] = epat(w);
    }
    // slice-0 prologue: 8 coalesced px/thread (491520 = 8 * 61440); ordered by init gridbar
    #pragma unroll
    for (int k = 0; k < 8; k++) {
        int p = k*NSLOT + u;
        float a0 = ff[p], a1 = ff[HWIMG + p];
        float on = on_at(fb, fb + HWIMG, a0, a1, p >> 10, p & 1023);
        unsigned m = __ballot_sync(0xffffffffu, on != 0.0f);
        if (lane == 0) __stcg(&g_on[p >> 5], m);
    }
    if (b == 0 && tid == 0) {
        unsigned e = atomicAdd(&g_epoch, 1u);
        g_tgt = (e + 1u) * (unsigned)TPS;          // publishes per run are exact (TPS/slice)
        g_tkb = atomicAdd(&g_ticket, 0u);          // snapshot absorbs past overshoot
    }
    // L2 prefetch of ff slice 0 (61440 threads x 64B == 2*HWIMG*4 bytes exactly)
    l2_prefetch((const char*)ff + (size_t)u * 64);
    gridbar_plain(b, tid);   // slice 0 + occupancy init + run bookkeeping visible
    const unsigned tgt = __ldcg(&g_tgt);
    const unsigned tkb = __ldcg(&g_tkb);

    for (int s = 0; s < SS - 1; s++) {
        const int par = s & 1;
        unsigned* bm = g_bits[s % 3];                  // marked here, read in B'(s)
        unsigned* bc = g_bits[(s + 1) % 3];            // cleared here (marked at A(s+1))
        const float* ff0 = ff + (size_t)s * 2 * HWIMG;
        const float* ff1 = ff0 + HWIMG;
        const unsigned* onw = g_on + s*WPI;

        // wait for this step's on-mask slice (slice 0 guaranteed by prologue+barrier)
        if (s >= 1) wait_slice(ff, fb, tid, s, tgt, tkb, &sh_tk, sh_w);

        // ===== Phase A: prefetch next ff slice, clear next buffer, advance, mark =====
        if (s < SS - 2)
            l2_prefetch((const char*)(ff + (size_t)(s + 1) * 2 * HWIMG) + (size_t)u * 64);
        if (b < 4) { int w = (b << 8) + tid; bc[w] = epat(w); }

        bool freeflag = true;                 // == (updated Start < 0)
        float xw = 0.0f, yw = 0.0f;
        if (mySt >= 0.0f) {
            BilW bw = mkw(myX, myY);
            // issue ALL 12 loads together (probes' indices depend only on bw)
            unsigned pw00 = onw[(bw.iy0<<5) + (bw.ix0>>5)];
            unsigned pw01 = onw[(bw.iy0<<5) + (bw.ix1>>5)];
            unsigned pw10 = onw[(bw.iy1<<5) + (bw.ix0>>5)];
            unsigned pw11 = onw[(bw.iy1<<5) + (bw.ix1>>5)];
            float u00 = ff0[bw.iy0*WW+bw.ix0], u01 = ff0[bw.iy0*WW+bw.ix1];
            float u10 = ff0[bw.iy1*WW+bw.ix0], u11 = ff0[bw.iy1*WW+bw.ix1];
            float v00 = ff1[bw.iy0*WW+bw.ix0], v01 = ff1[bw.iy0*WW+bw.ix1];
            float v10 = ff1[bw.iy1*WW+bw.ix0], v11 = ff1[bw.iy1*WW+bw.ix1];
            float uvx = bil4(u00, u01, u10, u11, bw.w00, bw.w01, bw.w10, bw.w11);
            float uvy = bil4(v00, v01, v10, v11, bw.w00, bw.w01, bw.w10, bw.w11);
            float xt = __fadd_rn(myX, uvx);
            float yt = __fadd_rn(myY, uvy);
            bool marg = (xt > (float)MARG) && (yt > (float)MARG) &&
                        (xt < (float)(WW - MARG)) && (yt < (float)(HH - MARG));
            if (marg) {
                float on00 = (float)((pw00 >> (bw.ix0&31)) & 1u);
                float on01 = (float)((pw01 >> (bw.ix1&31)) & 1u);
                float on10 = (float)((pw10 >> (bw.ix0&31)) & 1u);
                float on11 = (float)((pw11 >> (bw.ix1&31)) & 1u);
                float onv = bil4(on00, on01, on10, on11, bw.w00, bw.w01, bw.w10, bw.w11);
                if (onv > 0.5f) {
                    freeflag = false;
                    xw = xt; yw = yt;
                    int oy = (int)yt, ox = (int)xt;
                    int iylo = (oy - 9) / 4; if (iylo < 0) iylo = 0;
                    int iyhi = (oy - 8) / 4; if (iyhi > GYC-1) iyhi = GYC-1;
                    int ixlo = (ox - 9) / 4; if (ixlo < 0) ixlo = 0;
                    int ixhi = (ox - 8) / 4; if (ixhi > GXC-1) ixhi = GXC-1;
                    for (int iy = iylo; iy <= iyhi; iy++) {
                        int w = (iy << 3) + (ixlo >> 5);
                        unsigned m1 = 1u << (ixlo & 31);
                        if (ixhi > ixlo) {
                            if ((ixlo & 31) == 31) {
                                atomicOr(&bm[w], m1);
                                atomicOr(&bm[w + 1], 1u);
                            } else {
                                atomicOr(&bm[w], m1 | (m1 << 1));
                            }
                        } else {
                            atomicOr(&bm[w], m1);
                        }
                    }
                }
            }
        }
        if (freeflag) mySt = -1.0f;
        myX = xw; myY = yw;
        X[(s+1)*NSLOT + t] = xw;
        Y[(s+1)*NSLOT + t] = yw;

        unsigned amask = __ballot_sync(0xffffffffu, freeflag);
        if (lane == 0) g_slotCnt[par][wid][b] = __popc(amask);

        gridbar_steal(ff, fb, b, tid, tkb, &sh_tk, sh_w);   // arrive, then steal while waiting

        // ===== Phase B': full-map snapshot + local scan + slot ranking + self-birth =====
        uint4 v = __ldcg((const uint4*)bm + tid);
        sh_bits[tid*4 + 0] = v.x; sh_bits[tid*4 + 1] = v.y;
        sh_bits[tid*4 + 2] = v.z; sh_bits[tid*4 + 3] = v.w;
        int zc = 128 - (__popc(v.x) + __popc(v.y) + __popc(v.z) + __popc(v.w));

        int inc = zc;
        #pragma unroll
        for (int d = 1; d < 32; d <<= 1) {
            int n = __shfl_up_sync(0xffffffffu, inc, d);
            if (lane >= d) inc += n;
        }
        if (lane == 31) sh_wsum[wid] = inc;

        int rcnt = 0, rpre = 0;
        #pragma unroll
        for (int k = 0; k < 8; k++) {
            int i = lane + 32*k;
            if (i < BB) {
                int c = __ldcg(&g_slotCnt[par][wid][i]);
                rcnt += c;
                if (i < b) rpre += c;
            }
        }
        int rowtot = __reduce_add_sync(0xffffffffu, rcnt);
        int rowpre = __reduce_add_sync(0xffffffffu, rpre);
        if (lane == 0) sh_rowtot[wid] = rowtot;
        __syncthreads();
        if (tid == 0) {
            int run = 0;
            #pragma unroll
            for (int i = 0; i < NWARP; i++) { int c = sh_wsum[i]; sh_woff[i] = run; run += c; }
            sh_nc = run;
            int nfr = 0;
            #pragma unroll
            for (int i = 0; i < NWARP; i++) nfr += sh_rowtot[i];
            sh_nf = nfr;
        }
        __syncthreads();
        sh_pre[tid] = sh_woff[wid] + inc - zc;
        int base = rowpre;
        #pragma unroll
        for (int i = 0; i < NWARP; i++) if (i < wid) base += sh_rowtot[i];
        int myrank = freeflag ? base + __popc(amask & ((1u << lane) - 1u)) : -1;
        __syncthreads();

        // self-birth: k-th free slot takes the k-th zero bit (= k-th free candidate)
        int m = sh_nf < sh_nc ? sh_nf : sh_nc;
        if (myrank >= 0 && myrank < m) {
            int r = myrank;
            int lo = 0, hi = TT - 1;
            while (lo < hi) {
                int mid = (lo + hi + 1) >> 1;
                if (sh_pre[mid] <= r) lo = mid; else hi = mid - 1;
            }
            int k = r - sh_pre[lo];
            int wsel = -1, bit = 0;
            #pragma unroll
            for (int j = 0; j < 4; j++) {
                unsigned zw = ~sh_bits[lo*4 + j];
                int nz = __popc(zw);
                if (wsel < 0) {
                    if (k < nz) { wsel = lo*4 + j; bit = __fns(zw, 0, k + 1); }
                    else k -= nz;
                }
            }
            int iy = wsel >> 3;
            int ix = ((wsel & 7) << 5) | bit;
            myX = (float)(MARG + 4*ix);
            myY = (float)(MARG + 4*iy);
            mySt = (float)(s + 1);
            X[(s+1)*NSLOT + t] = myX;
            Y[(s+1)*NSLOT + t] = myY;
        }
        // no second barrier: everything phase C needed was block-local.
    }

    St[t] = mySt;
}

extern "C" void kernel_launch(void* const* d_in, const int* in_sizes, int n_in,
                              void* d_out, int out_size) {
    (void)in_sizes; (void)n_in; (void)out_size;
    const float* ff = (const float*)d_in[0];
    const float* fb = (const float*)d_in[1];
    float* out = (float*)d_out;
    k_linker<<<BB, TT>>>(ff, fb, out);
}